// round 16
// baseline (speedup 1.0000x reference)
#include <cuda_runtime.h>
#include <math.h>

#define BMAX 128
#define PMAX 8732
#define NOBJ 16
#define CLS  21
#define NB   1024
#define K3T  1024
#define BUFCAP 2048
#define MCH   8      // match chunks per batch
#define CROWS 256    // rows per k_conf block

// ---------------- scratch (static device globals; no runtime alloc) ----------------
__device__ float              g_true_locs[BMAX * PMAX * 4];
__device__ unsigned char      g_true_cls[BMAX * PMAX];
__device__ float              g_conf_neg[BMAX * PMAX];
__device__ int                g_npos[BMAX];
__device__ unsigned long long g_obj_best[BMAX * NOBJ];   // (iou_bits<<32)|~p
__device__ float              g_pos_sum;
__device__ float              g_loc_sum;
__device__ float              g_hard_sum;

// ---------------- kernel 0: zero accumulators ----------------
__global__ void k_init(int B) {
    int t = blockIdx.x * blockDim.x + threadIdx.x;
    if (t < B * NOBJ) g_obj_best[t] = 0ull;
    if (t < B) g_npos[t] = 0;
    if (t == 0) { g_pos_sum = 0.f; g_loc_sum = 0.f; g_hard_sum = 0.f; }
}

// ---------------- kernel 1: matching (B x MCH blocks, 256 threads) ----------------
__global__ void k_match(const float* __restrict__ boxes,
                        const int*   __restrict__ labels,
                        const float* __restrict__ priors,
                        int P) {
    int b  = blockIdx.x / MCH;
    int ch = blockIdx.x % MCH;
    int CS = (P + MCH - 1) / MCH;
    int p0 = ch * CS;
    int p1 = min(p0 + CS, P);

    __shared__ float bx1[NOBJ], by1[NOBJ], bx2[NOBJ], by2[NOBJ], barea[NOBJ];
    __shared__ int   blab[NOBJ];
    __shared__ float wv[8][NOBJ];
    __shared__ int   wi[8][NOBJ];

    int tid = threadIdx.x;
    if (tid < NOBJ) {
        const float* bb = boxes + ((long long)b * NOBJ + tid) * 4;
        float x1 = bb[0], y1 = bb[1], x2 = bb[2], y2 = bb[3];
        bx1[tid] = x1; by1[tid] = y1; bx2[tid] = x2; by2[tid] = y2;
        barea[tid] = (x2 - x1) * (y2 - y1);
        blab[tid]  = labels[b * NOBJ + tid];
    }
    __syncthreads();

    // per-object best prior (this thread's slice; strictly-greater keeps smallest p)
    float obv[NOBJ];
    int   obp[NOBJ];
#pragma unroll
    for (int n = 0; n < NOBJ; n++) { obv[n] = -1.f; obp[n] = 0x7fffffff; }

    for (int p = p0 + tid; p < p1; p += blockDim.x) {
        float pcx = priors[p * 4 + 0], pcy = priors[p * 4 + 1];
        float pw  = priors[p * 4 + 2], ph  = priors[p * 4 + 3];
        float px1 = pcx - pw * 0.5f, py1 = pcy - ph * 0.5f;
        float px2 = pcx + pw * 0.5f, py2 = pcy + ph * 0.5f;
        float parea = (px2 - px1) * (py2 - py1);

        float bestv = -1.f; int besto = 0;
#pragma unroll
        for (int n = 0; n < NOBJ; n++) {
            float lx = fmaxf(bx1[n], px1), ly = fmaxf(by1[n], py1);
            float hx = fminf(bx2[n], px2), hy = fminf(by2[n], py2);
            float iw = fmaxf(hx - lx, 0.f), ih = fmaxf(hy - ly, 0.f);
            float inter = iw * ih;
            float iou = inter / (barea[n] + parea - inter);
            if (iou > bestv) { bestv = iou; besto = n; }     // first-index tie-break
            if (iou > obv[n]) { obv[n] = iou; obp[n] = p; }
        }
        int lab = (bestv < 0.5f) ? 0 : blab[besto];
        g_true_cls[b * P + p] = (unsigned char)lab;
        if (lab) {
            float mx1 = bx1[besto], my1 = by1[besto], mx2 = bx2[besto], my2 = by2[besto];
            float mcx = (mx1 + mx2) * 0.5f, mcy = (my1 + my2) * 0.5f;
            float mw = mx2 - mx1, mh = my2 - my1;
            float* tl = g_true_locs + ((long long)(b * P + p)) * 4;
            tl[0] = (mcx - pcx) / (pw / 10.0f);
            tl[1] = (mcy - pcy) / (ph / 10.0f);
            tl[2] = __logf(mw / pw) * 5.0f;
            tl[3] = __logf(mh / ph) * 5.0f;
        }
    }

    // block-wide per-object argmax (value desc, smallest prior index on tie)
    int lane = tid & 31, wid = tid >> 5;
#pragma unroll
    for (int n = 0; n < NOBJ; n++) {
        float v = obv[n]; int idx = obp[n];
#pragma unroll
        for (int off = 16; off; off >>= 1) {
            float ov = __shfl_down_sync(0xffffffffu, v, off);
            int   oi = __shfl_down_sync(0xffffffffu, idx, off);
            if (ov > v || (ov == v && oi < idx)) { v = ov; idx = oi; }
        }
        if (lane == 0) { wv[wid][n] = v; wi[wid][n] = idx; }
    }
    __syncthreads();
    int nw = blockDim.x >> 5;
    if (tid < NOBJ) {
        float v = wv[0][tid]; int idx = wi[0][tid];
        for (int w = 1; w < nw; w++) {
            float ov = wv[w][tid]; int oi = wi[w][tid];
            if (ov > v || (ov == v && oi < idx)) { v = ov; idx = oi; }
        }
        if (idx != 0x7fffffff) {
            // key: higher iou wins; on equal iou, larger ~p wins -> smaller p wins
            unsigned long long key =
                ((unsigned long long)__float_as_uint(fmaxf(v, 0.f)) << 32) |
                (unsigned int)(~(unsigned int)idx);
            atomicMax(&g_obj_best[b * NOBJ + tid], key);
        }
    }
}

// ---------------- kernel 1b: forced-prior override (sequential last-wins) ----------------
__global__ void k_override(const float* __restrict__ boxes,
                           const int*   __restrict__ labels,
                           const float* __restrict__ priors,
                           int P) {
    int b = blockIdx.x;
    if (threadIdx.x != 0) return;
    for (int n = 0; n < NOBJ; n++) {
        unsigned long long key = g_obj_best[b * NOBJ + n];
        int p = (int)(~(unsigned int)(key & 0xFFFFFFFFull));
        g_true_cls[b * P + p] = (unsigned char)labels[b * NOBJ + n];
        const float* bb = boxes + ((long long)b * NOBJ + n) * 4;
        float x1 = bb[0], y1 = bb[1], x2 = bb[2], y2 = bb[3];
        float pcx = priors[p * 4 + 0], pcy = priors[p * 4 + 1];
        float pw  = priors[p * 4 + 2], ph  = priors[p * 4 + 3];
        float mcx = (x1 + x2) * 0.5f, mcy = (y1 + y2) * 0.5f;
        float mw = x2 - x1, mh = y2 - y1;
        float* tl = g_true_locs + ((long long)(b * P + p)) * 4;
        tl[0] = (mcx - pcx) / (pw / 10.0f);
        tl[1] = (mcy - pcy) / (ph / 10.0f);
        tl[2] = __logf(mw / pw) * 5.0f;
        tl[3] = __logf(mh / ph) * 5.0f;
    }
}

// ---------------- kernel 2: per-prior cross-entropy + positives ----------------
__global__ void __launch_bounds__(CROWS) k_conf(const float* __restrict__ scores,
                                                const float* __restrict__ plocs,
                                                int P, int total) {
    __shared__ float s[CROWS * CLS];
    int tid = threadIdx.x;

    // vectorized coalesced staging: CROWS*CLS floats = CROWS*CLS/4 float4 (exact)
    const float4* src4 = (const float4*)(scores) + (long long)blockIdx.x * (CROWS * CLS / 4);
    float4* s4 = (float4*)s;
#pragma unroll
    for (int i = tid; i < CROWS * CLS / 4; i += CROWS) {
        s4[i] = src4[i];
    }
    __syncthreads();

    int g = blockIdx.x * CROWS + tid;
    if (g >= total) return;

    const float* row = s + tid * CLS;
    float m = row[0];
#pragma unroll
    for (int j = 1; j < CLS; j++) m = fmaxf(m, row[j]);
    float se = 0.f;
#pragma unroll
    for (int j = 0; j < CLS; j++) se += __expf(row[j] - m);

    int cls = (int)g_true_cls[g];
    float conf = m + __logf(se) - row[cls];

    if (cls != 0) {
        g_conf_neg[g] = 0.f;                 // matches reference's masked array
        atomicAdd(&g_pos_sum, conf);
        atomicAdd(&g_npos[g / P], 1);
        float ls = 0.f;
#pragma unroll
        for (int d = 0; d < 4; d++) {
            float dd = plocs[(long long)g * 4 + d] - g_true_locs[(long long)g * 4 + d];
            float ad = fabsf(dd);
            ls += (ad < 1.f) ? 0.5f * dd * dd : ad - 0.5f;
        }
        atomicAdd(&g_loc_sum, ls);
    } else {
        g_conf_neg[g] = conf;
    }
}

// ---------------- kernel 3: exact hard-negative top-k sum (one block per batch) ----------------
__device__ __forceinline__ int clampbin(float v, float lo, float scale) {
    int bb = (int)((v - lo) * scale);
    bb = bb < 0 ? 0 : bb;
    bb = bb > NB - 1 ? NB - 1 : bb;
    return bb;
}

__global__ void k_hard(int P) {
    __shared__ float sv[PMAX];
    __shared__ int   s_suf[NB];
    __shared__ float s_buf[BUFCAP];
    __shared__ float s_red[32];
    __shared__ float s_hard, s_vmax;
    __shared__ int   s_ctr, s_t, s_above, s_cntt, s_k;

    int b = blockIdx.x;
    int tid = threadIdx.x;
    const float* src = g_conf_neg + (size_t)b * P;

    float vmax = 0.f;
    for (int i = tid; i < P; i += K3T) {
        float v = src[i]; sv[i] = v; vmax = fmaxf(vmax, v);
    }
#pragma unroll
    for (int off = 16; off; off >>= 1) vmax = fmaxf(vmax, __shfl_xor_sync(0xffffffffu, vmax, off));
    if ((tid & 31) == 0) s_red[tid >> 5] = vmax;
    if (tid == 0) {
        s_hard = 0.f;
        int k = 3 * g_npos[b];
        s_k = k < P ? k : P;
    }
    __syncthreads();
    if (tid == 0) {
        float vm = s_red[0];
        for (int w = 1; w < K3T / 32; w++) vm = fmaxf(vm, s_red[w]);
        s_vmax = vm;
    }
    __syncthreads();

    int k = s_k;
    if (k <= 0) return;

    float lo = 0.f, hi = s_vmax * 1.000001f + 1e-30f;
    float lv_lo[4], lv_scale[4];
    int   lv_t[4];
    int depth = 0;

    for (int iter = 0; iter < 4; iter++) {
        s_suf[tid] = 0;
        __syncthreads();
        float scale = (float)NB / (hi - lo);

        for (int i = tid; i < P; i += K3T) {
            float v = sv[i];
            bool mem = true;
            for (int d = 0; d < depth; d++)
                if (clampbin(v, lv_lo[d], lv_scale[d]) != lv_t[d]) { mem = false; break; }
            if (mem) atomicAdd(&s_suf[clampbin(v, lo, scale)], 1);
        }
        __syncthreads();

        for (int off = 1; off < NB; off <<= 1) {
            int add = (tid + off < NB) ? s_suf[tid + off] : 0;
            __syncthreads();
            s_suf[tid] += add;
            __syncthreads();
        }

        int above = (tid < NB - 1) ? s_suf[tid + 1] : 0;
        int cnt = s_suf[tid] - above;
        if (above < k && above + cnt >= k) { s_t = tid; s_above = above; s_cntt = cnt; }
        if (tid == 0) s_ctr = 0;
        __syncthreads();

        int t = s_t;
        int r = k - s_above;
        int m = s_cntt;
        bool finalpass = (m <= 256) || (iter == 3);

        float part = 0.f;
        for (int i = tid; i < P; i += K3T) {
            float v = sv[i];
            bool mem = true;
            for (int d = 0; d < depth; d++)
                if (clampbin(v, lv_lo[d], lv_scale[d]) != lv_t[d]) { mem = false; break; }
            if (!mem) continue;
            int bb = clampbin(v, lo, scale);
            if (bb > t) part += v;
            else if (bb == t && finalpass) {
                int pidx = atomicAdd(&s_ctr, 1);
                if (pidx < BUFCAP) s_buf[pidx] = v;
            }
        }
#pragma unroll
        for (int off = 16; off; off >>= 1) part += __shfl_xor_sync(0xffffffffu, part, off);
        if ((tid & 31) == 0) atomicAdd(&s_hard, part);
        __syncthreads();

        if (finalpass) {
            if (tid == 0) {
                int mm = s_ctr < BUFCAP ? s_ctr : BUFCAP;
                int rr = r < mm ? r : mm;
                float vfirst = (mm > 0) ? s_buf[0] : 0.f;
                float acc = 0.f;
                for (int sel = 0; sel < rr; sel++) {
                    float bestv = -1.f; int besti = 0;
                    for (int q = 0; q < mm; q++)
                        if (s_buf[q] > bestv) { bestv = s_buf[q]; besti = q; }
                    acc += bestv;
                    s_buf[besti] = -1.f;
                }
                if (rr < r) acc += (float)(r - rr) * vfirst;
                atomicAdd(&g_hard_sum, s_hard + acc);
            }
            break;
        }
        lv_lo[depth] = lo; lv_scale[depth] = scale; lv_t[depth] = t; depth++;
        float binw = (hi - lo) / (float)NB;
        float nlo = lo + (float)t * binw;
        float nhi = lo + (float)(t + 1) * binw;
        lo = nlo; hi = (nhi > nlo) ? nhi : (nlo + 1e-30f);
        k = r;
        __syncthreads();
    }
}

// ---------------- kernel 4: combine ----------------
__global__ void k_final(float* __restrict__ out, int B) {
    if (threadIdx.x == 0) {
        int tot = 0;
        for (int b = 0; b < B; b++) tot += g_npos[b];
        float np = (float)tot;
        out[0] = (g_hard_sum + g_pos_sum) / np + g_loc_sum / (np * 4.0f);
    }
}

// ---------------- launcher ----------------
extern "C" void kernel_launch(void* const* d_in, const int* in_sizes, int n_in,
                              void* d_out, int out_size) {
    const float* plocs  = (const float*)d_in[0];
    const float* scores = (const float*)d_in[1];
    const float* boxes  = (const float*)d_in[2];
    const int*   labels = (const int*)d_in[3];
    const float* priors = (const float*)d_in[4];
    float* out = (float*)d_out;

    int P = in_sizes[4] / 4;                 // 8732
    int B = in_sizes[0] / (P * 4);           // 128
    int total = B * P;

    k_init<<<(B * NOBJ + 1023) / 1024, 1024>>>(B);
    k_match<<<B * MCH, 256>>>(boxes, labels, priors, P);
    k_override<<<B, 32>>>(boxes, labels, priors, P);
    k_conf<<<(total + CROWS - 1) / CROWS, CROWS>>>(scores, plocs, P, total);
    k_hard<<<B, K3T>>>(P);
    k_final<<<1, 32>>>(out, B);
}

// round 17
// speedup vs baseline: 1.4612x; 1.4612x over previous
#include <cuda_runtime.h>
#include <math.h>

#define BMAX 128
#define PMAX 8732
#define NOBJ 16
#define CLS  21
#define NB   1024
#define K3T  1024
#define BUFCAP 2048
#define CROWS 512    // rows per k_conf block

// ---------------- scratch (static device globals; no runtime alloc) ----------------
__device__ float         g_true_locs[BMAX * PMAX * 4];
__device__ unsigned char g_true_cls[BMAX * PMAX];
__device__ float         g_conf_neg[BMAX * PMAX];
__device__ int           g_npos[BMAX];
__device__ float         g_pos_sum;
__device__ float         g_loc_sum;
__device__ float         g_hard_sum;

// ---------------- kernel 1: init + matching + override (one block per batch) ----------------
__global__ void __launch_bounds__(1024) k_match(const float* __restrict__ boxes,
                                                const int*   __restrict__ labels,
                                                const float* __restrict__ priors,
                                                int P) {
    int b = blockIdx.x;
    __shared__ float bx1[NOBJ], by1[NOBJ], bx2[NOBJ], by2[NOBJ], barea[NOBJ];
    __shared__ int   blab[NOBJ];
    __shared__ float wv[32][NOBJ];
    __shared__ int   wi[32][NOBJ];
    __shared__ int   pfe[NOBJ];
    __shared__ float spri[NOBJ][4];

    int tid = threadIdx.x;
    if (b == 0 && tid == 0) { g_pos_sum = 0.f; g_loc_sum = 0.f; g_hard_sum = 0.f; }
    if (tid == 0) g_npos[b] = 0;
    if (tid < NOBJ) {
        const float* bb = boxes + ((long long)b * NOBJ + tid) * 4;
        float x1 = bb[0], y1 = bb[1], x2 = bb[2], y2 = bb[3];
        bx1[tid] = x1; by1[tid] = y1; bx2[tid] = x2; by2[tid] = y2;
        barea[tid] = (x2 - x1) * (y2 - y1);
        blab[tid]  = labels[b * NOBJ + tid];
    }
    __syncthreads();

    // per-object best prior (this thread's slice; strictly-greater keeps smallest p)
    float obv[NOBJ];
    int   obp[NOBJ];
#pragma unroll
    for (int n = 0; n < NOBJ; n++) { obv[n] = -1.f; obp[n] = 0x7fffffff; }

    for (int p = tid; p < P; p += blockDim.x) {
        float4 pr = ((const float4*)priors)[p];
        float pcx = pr.x, pcy = pr.y, pw = pr.z, ph = pr.w;
        float px1 = pcx - pw * 0.5f, py1 = pcy - ph * 0.5f;
        float px2 = pcx + pw * 0.5f, py2 = pcy + ph * 0.5f;
        float parea = (px2 - px1) * (py2 - py1);

        float bestv = -1.f; int besto = 0;
#pragma unroll
        for (int n = 0; n < NOBJ; n++) {
            float lx = fmaxf(bx1[n], px1), ly = fmaxf(by1[n], py1);
            float hx = fminf(bx2[n], px2), hy = fminf(by2[n], py2);
            float iw = fmaxf(hx - lx, 0.f), ih = fmaxf(hy - ly, 0.f);
            float inter = iw * ih;
            float iou = inter / (barea[n] + parea - inter);   // exact div: decisions bit-stable
            if (iou > bestv) { bestv = iou; besto = n; }       // first-index tie-break
            if (iou > obv[n]) { obv[n] = iou; obp[n] = p; }
        }
        int lab = (bestv < 0.5f) ? 0 : blab[besto];
        g_true_cls[b * P + p] = (unsigned char)lab;
        if (lab) {
            float mx1 = bx1[besto], my1 = by1[besto], mx2 = bx2[besto], my2 = by2[besto];
            float mcx = (mx1 + mx2) * 0.5f, mcy = (my1 + my2) * 0.5f;
            float mw = mx2 - mx1, mh = my2 - my1;
            float* tl = g_true_locs + ((long long)(b * P + p)) * 4;
            tl[0] = (mcx - pcx) / (pw / 10.0f);
            tl[1] = (mcy - pcy) / (ph / 10.0f);
            tl[2] = __logf(mw / pw) * 5.0f;
            tl[3] = __logf(mh / ph) * 5.0f;
        }
    }

    // block-wide per-object argmax (value desc, smallest prior index on tie)
    int lane = tid & 31, wid = tid >> 5;
#pragma unroll
    for (int n = 0; n < NOBJ; n++) {
        float v = obv[n]; int idx = obp[n];
#pragma unroll
        for (int off = 16; off; off >>= 1) {
            float ov = __shfl_down_sync(0xffffffffu, v, off);
            int   oi = __shfl_down_sync(0xffffffffu, idx, off);
            if (ov > v || (ov == v && oi < idx)) { v = ov; idx = oi; }
        }
        if (lane == 0) { wv[wid][n] = v; wi[wid][n] = idx; }
    }
    __syncthreads();
    int nw = blockDim.x >> 5;
    if (tid < NOBJ) {
        float v = wv[0][tid]; int idx = wi[0][tid];
        for (int w = 1; w < nw; w++) {
            float ov = wv[w][tid]; int oi = wi[w][tid];
            if (ov > v || (ov == v && oi < idx)) { v = ov; idx = oi; }
        }
        pfe[tid] = idx;
    }
    __syncthreads();
    // prefetch chosen priors into smem (parallel loads)
    if (tid < NOBJ) {
        float4 pr = ((const float4*)priors)[pfe[tid]];
        spri[tid][0] = pr.x; spri[tid][1] = pr.y; spri[tid][2] = pr.z; spri[tid][3] = pr.w;
    }
    __syncthreads();

    // forced-prior override (sequential => last-wins on duplicate priors; smem-only reads)
    if (tid == 0) {
#pragma unroll
        for (int n = 0; n < NOBJ; n++) {
            int p = pfe[n];
            g_true_cls[b * P + p] = (unsigned char)blab[n];
            float pcx = spri[n][0], pcy = spri[n][1], pw = spri[n][2], ph = spri[n][3];
            float mcx = (bx1[n] + bx2[n]) * 0.5f, mcy = (by1[n] + by2[n]) * 0.5f;
            float mw = bx2[n] - bx1[n], mh = by2[n] - by1[n];
            float* tl = g_true_locs + ((long long)(b * P + p)) * 4;
            tl[0] = (mcx - pcx) / (pw / 10.0f);
            tl[1] = (mcy - pcy) / (ph / 10.0f);
            tl[2] = __logf(mw / pw) * 5.0f;
            tl[3] = __logf(mh / ph) * 5.0f;
        }
    }
}

// ---------------- kernel 2: per-prior cross-entropy + positives ----------------
__global__ void __launch_bounds__(CROWS) k_conf(const float* __restrict__ scores,
                                                const float* __restrict__ plocs,
                                                int P, int total) {
    __shared__ float s[CROWS * CLS];
    int tid = threadIdx.x;

    // vectorized coalesced staging: CROWS*CLS/4 float4 per block (CLS*CROWS % 4 == 0)
    const float4* src4 = (const float4*)(scores) + (long long)blockIdx.x * (CROWS * CLS / 4);
    long long lim4 = ((long long)total * CLS) / 4 - (long long)blockIdx.x * (CROWS * CLS / 4);
    float4* s4 = (float4*)s;
#pragma unroll
    for (int i = tid; i < CROWS * CLS / 4; i += CROWS) {
        if (i < lim4) s4[i] = src4[i];
    }
    __syncthreads();

    int g = blockIdx.x * CROWS + tid;
    if (g >= total) return;

    const float* row = s + tid * CLS;
    float m = row[0];
#pragma unroll
    for (int j = 1; j < CLS; j++) m = fmaxf(m, row[j]);
    float se = 0.f;
#pragma unroll
    for (int j = 0; j < CLS; j++) se += __expf(row[j] - m);

    int cls = (int)g_true_cls[g];
    float conf = m + __logf(se) - row[cls];

    if (cls != 0) {
        g_conf_neg[g] = 0.f;                 // matches reference's masked array
        atomicAdd(&g_pos_sum, conf);
        atomicAdd(&g_npos[g / P], 1);
        float ls = 0.f;
#pragma unroll
        for (int d = 0; d < 4; d++) {
            float dd = plocs[(long long)g * 4 + d] - g_true_locs[(long long)g * 4 + d];
            float ad = fabsf(dd);
            ls += (ad < 1.f) ? 0.5f * dd * dd : ad - 0.5f;
        }
        atomicAdd(&g_loc_sum, ls);
    } else {
        g_conf_neg[g] = conf;
    }
}

// ---------------- kernel 3: exact hard-negative top-k sum (one block per batch) ----------------
__device__ __forceinline__ int clampbin(float v, float lo, float scale) {
    int bb = (int)((v - lo) * scale);
    bb = bb < 0 ? 0 : bb;
    bb = bb > NB - 1 ? NB - 1 : bb;
    return bb;
}

__global__ void __launch_bounds__(K3T) k_hard(int P) {
    __shared__ float sv[PMAX];
    __shared__ int   s_suf[NB];
    __shared__ float s_buf[BUFCAP];
    __shared__ float s_red[32];
    __shared__ float s_hard, s_vmax;
    __shared__ int   s_ctr, s_t, s_above, s_cntt, s_k;

    int b = blockIdx.x;
    int tid = threadIdx.x;
    // P % 4 == 0 and b*P*4 bytes is 16B-aligned (P=8732 -> b*34928 % 16 == 0)
    const float4* src4 = (const float4*)(g_conf_neg + (size_t)b * P);
    int P4 = P >> 2;

    float vmax = 0.f;
    float4* sv4 = (float4*)sv;
    for (int i = tid; i < P4; i += K3T) {
        float4 v = src4[i]; sv4[i] = v;
        vmax = fmaxf(vmax, fmaxf(fmaxf(v.x, v.y), fmaxf(v.z, v.w)));
    }
#pragma unroll
    for (int off = 16; off; off >>= 1) vmax = fmaxf(vmax, __shfl_xor_sync(0xffffffffu, vmax, off));
    if ((tid & 31) == 0) s_red[tid >> 5] = vmax;
    if (tid == 0) {
        s_hard = 0.f;
        int k = 3 * g_npos[b];
        s_k = k < P ? k : P;
    }
    __syncthreads();
    if (tid == 0) {
        float vm = s_red[0];
        for (int w = 1; w < K3T / 32; w++) vm = fmaxf(vm, s_red[w]);
        s_vmax = vm;
    }
    __syncthreads();

    int k = s_k;
    if (k <= 0) return;

    float lo = 0.f, hi = s_vmax * 1.000001f + 1e-30f;
    float lv_lo[4], lv_scale[4];
    int   lv_t[4];
    int depth = 0;

    for (int iter = 0; iter < 4; iter++) {
        s_suf[tid] = 0;
        __syncthreads();
        float scale = (float)NB / (hi - lo);

        for (int i = tid; i < P; i += K3T) {
            float v = sv[i];
            bool mem = true;
            for (int d = 0; d < depth; d++)
                if (clampbin(v, lv_lo[d], lv_scale[d]) != lv_t[d]) { mem = false; break; }
            if (mem) atomicAdd(&s_suf[clampbin(v, lo, scale)], 1);
        }
        __syncthreads();

        for (int off = 1; off < NB; off <<= 1) {
            int add = (tid + off < NB) ? s_suf[tid + off] : 0;
            __syncthreads();
            s_suf[tid] += add;
            __syncthreads();
        }

        int above = (tid < NB - 1) ? s_suf[tid + 1] : 0;
        int cnt = s_suf[tid] - above;
        if (above < k && above + cnt >= k) { s_t = tid; s_above = above; s_cntt = cnt; }
        if (tid == 0) s_ctr = 0;
        __syncthreads();

        int t = s_t;
        int r = k - s_above;
        int m = s_cntt;
        bool finalpass = (m <= 256) || (iter == 3);

        float part = 0.f;
        for (int i = tid; i < P; i += K3T) {
            float v = sv[i];
            bool mem = true;
            for (int d = 0; d < depth; d++)
                if (clampbin(v, lv_lo[d], lv_scale[d]) != lv_t[d]) { mem = false; break; }
            if (!mem) continue;
            int bb = clampbin(v, lo, scale);
            if (bb > t) part += v;
            else if (bb == t && finalpass) {
                int pidx = atomicAdd(&s_ctr, 1);
                if (pidx < BUFCAP) s_buf[pidx] = v;
            }
        }
#pragma unroll
        for (int off = 16; off; off >>= 1) part += __shfl_xor_sync(0xffffffffu, part, off);
        if ((tid & 31) == 0) atomicAdd(&s_hard, part);
        __syncthreads();

        if (finalpass) {
            if (tid == 0) {
                int mm = s_ctr < BUFCAP ? s_ctr : BUFCAP;
                int rr = r < mm ? r : mm;
                float vfirst = (mm > 0) ? s_buf[0] : 0.f;
                float acc = 0.f;
                for (int sel = 0; sel < rr; sel++) {
                    float bestv = -1.f; int besti = 0;
                    for (int q = 0; q < mm; q++)
                        if (s_buf[q] > bestv) { bestv = s_buf[q]; besti = q; }
                    acc += bestv;
                    s_buf[besti] = -1.f;
                }
                if (rr < r) acc += (float)(r - rr) * vfirst;
                atomicAdd(&g_hard_sum, s_hard + acc);
            }
            break;
        }
        lv_lo[depth] = lo; lv_scale[depth] = scale; lv_t[depth] = t; depth++;
        float binw = (hi - lo) / (float)NB;
        float nlo = lo + (float)t * binw;
        float nhi = lo + (float)(t + 1) * binw;
        lo = nlo; hi = (nhi > nlo) ? nhi : (nlo + 1e-30f);
        k = r;
        __syncthreads();
    }
}

// ---------------- kernel 4: combine (parallel reduce of n_pos) ----------------
__global__ void k_final(float* __restrict__ out, int B) {
    __shared__ int sred[4];
    int tid = threadIdx.x;                   // 128 threads
    int v = (tid < B) ? g_npos[tid] : 0;
#pragma unroll
    for (int off = 16; off; off >>= 1) v += __shfl_xor_sync(0xffffffffu, v, off);
    if ((tid & 31) == 0) sred[tid >> 5] = v;
    __syncthreads();
    if (tid == 0) {
        int tot = sred[0] + sred[1] + sred[2] + sred[3];
        float np = (float)tot;
        out[0] = (g_hard_sum + g_pos_sum) / np + g_loc_sum / (np * 4.0f);
    }
}

// ---------------- launcher ----------------
extern "C" void kernel_launch(void* const* d_in, const int* in_sizes, int n_in,
                              void* d_out, int out_size) {
    const float* plocs  = (const float*)d_in[0];
    const float* scores = (const float*)d_in[1];
    const float* boxes  = (const float*)d_in[2];
    const int*   labels = (const int*)d_in[3];
    const float* priors = (const float*)d_in[4];
    float* out = (float*)d_out;

    int P = in_sizes[4] / 4;                 // 8732
    int B = in_sizes[0] / (P * 4);           // 128
    int total = B * P;

    k_match<<<B, 1024>>>(boxes, labels, priors, P);
    k_conf<<<(total + CROWS - 1) / CROWS, CROWS>>>(scores, plocs, P, total);
    k_hard<<<B, K3T>>>(P);
    k_final<<<1, 128>>>(out, B);
}